// round 1
// baseline (speedup 1.0000x reference)
#include <cuda_runtime.h>
#include <math.h>
#include <stdint.h>

// ---------------------------------------------------------------------------
// DGCNN forward, B=8, C=3, N=2048, K=20
// Pipeline (17 graph nodes):
//   zero_stats
//   knn_feat                      -> g_h0 [327680, 6]
//   conv<6>   + stats             -> g_y  [327680, 64]
//   finalize1 ; apply1 (+max)     -> g_h (64ch), g_cat[:,0:64]
//   conv<64>  + stats             -> g_y 64
//   finalize2 ; apply2            -> g_h (64ch), g_cat[:,64:128]
//   conv<64->128> + stats         -> g_y 128
//   finalize3 ; apply3            -> g_h (128ch), g_cat[:,128:256]
//   conv<128->256> + stats        -> g_y 256
//   finalize4 ; apply4 (max only) -> g_cat[:,256:512]
//   conv<512->1024> + stats       -> g_y (16384x1024)
//   finalize5 ; apply5 (BN+LReLU+transpose) -> d_out [8,1024,2048]
// ---------------------------------------------------------------------------

#define B_      8
#define N_      2048
#define KNN_    20
#define ROWS_   (B_ * N_)                 // 16384
#define M1_     (ROWS_ * KNN_)            // 327680

// Static device scratch (allocation-free rule: __device__ globals)
__device__ float  g_h0[M1_ * 6];          // 7.9 MB
__device__ float  g_h [M1_ * 128];        // 167.8 MB (h1/h2/h3 pool)
__device__ float  g_y [M1_ * 256];        // 335.5 MB (y1..y4, y5 reuses)
__device__ float  g_cat[ROWS_ * 512];     // 33.5 MB
__device__ double g_sum[1536];
__device__ double g_sq [1536];
__device__ float  g_scale[1536];
__device__ float  g_bias [1536];

// stage stat offsets: s1=0(64) s2=64(64) s3=128(128) s4=256(256) s5=512(1024)

// ---------------------------------------------------------------------------
__global__ void zero_stats_kernel() {
    int t = blockIdx.x * blockDim.x + threadIdx.x;
    if (t < 1536) { g_sum[t] = 0.0; g_sq[t] = 0.0; }
}

// ---------------------------------------------------------------------------
// kNN + edge features. One block per (point i, batch b). 256 threads.
// dist[j] = 2*<xi,xj> - |xi|^2 - |xj|^2 (same formula as reference).
// 20 rounds of masked block-argmax (lowest index wins ties).
// Order of neighbors is irrelevant downstream (conv/BN/max are k-symmetric).
// ---------------------------------------------------------------------------
__global__ void __launch_bounds__(256) knn_feat_kernel(const float* __restrict__ x) {
    __shared__ float xs0[N_], xs1[N_], xs2[N_];
    __shared__ float dist[N_];
    __shared__ float wval[8];
    __shared__ int   widx[8];
    __shared__ int   sel[KNN_];

    const int b = blockIdx.y;
    const int i = blockIdx.x;
    const int tid = threadIdx.x;
    const float* xb = x + (size_t)b * 3 * N_;

    for (int j = tid; j < N_; j += 256) {
        xs0[j] = xb[j];
        xs1[j] = xb[N_ + j];
        xs2[j] = xb[2 * N_ + j];
    }
    __syncthreads();

    const float p0 = xs0[i], p1 = xs1[i], p2 = xs2[i];
    const float xxi = p0 * p0 + p1 * p1 + p2 * p2;

    for (int j = tid; j < N_; j += 256) {
        float q0 = xs0[j], q1 = xs1[j], q2 = xs2[j];
        float inner = p0 * q0 + p1 * q1 + p2 * q2;
        float xxj = q0 * q0 + q1 * q1 + q2 * q2;
        dist[j] = 2.0f * inner - xxi - xxj;
    }
    __syncthreads();

    const int lane = tid & 31, warp = tid >> 5;
    for (int t = 0; t < KNN_; t++) {
        float v = -3.0e38f; int bj = N_;
        for (int j = tid; j < N_; j += 256) {
            float d = dist[j];
            if (d > v || (d == v && j < bj)) { v = d; bj = j; }
        }
        #pragma unroll
        for (int s = 16; s > 0; s >>= 1) {
            float ov = __shfl_down_sync(0xffffffffu, v, s);
            int   oj = __shfl_down_sync(0xffffffffu, bj, s);
            if (ov > v || (ov == v && oj < bj)) { v = ov; bj = oj; }
        }
        if (lane == 0) { wval[warp] = v; widx[warp] = bj; }
        __syncthreads();
        if (tid == 0) {
            float bv = wval[0]; int bbj = widx[0];
            #pragma unroll
            for (int w = 1; w < 8; w++)
                if (wval[w] > bv || (wval[w] == bv && widx[w] < bbj)) { bv = wval[w]; bbj = widx[w]; }
            sel[t] = bbj;
            dist[bbj] = -3.3e38f;
        }
        __syncthreads();
    }

    // write h0[(b,i,k), c]: c<3: xj - xi ; c>=3: xi
    for (int e = tid; e < KNN_ * 6; e += 256) {
        int kk = e / 6, c = e - kk * 6;
        int j = sel[kk];
        float val;
        if      (c == 0) val = xs0[j] - p0;
        else if (c == 1) val = xs1[j] - p1;
        else if (c == 2) val = xs2[j] - p2;
        else if (c == 3) val = p0;
        else if (c == 4) val = p1;
        else             val = p2;
        g_h0[(((size_t)b * N_ + i) * KNN_ + kk) * 6 + c] = val;
    }
}

// ---------------------------------------------------------------------------
// Tiled SGEMM: Y[m, n0+n] = sum_c A[m, c] * W[n0+n, c]
// MTILE=128, 256 threads (16x16), per-thread 8 x (NTILE/16).
// Fuses per-channel sum/sumsq accumulation (double atomics).
// M divisible by 128, COUT divisible by NTILE (true for all stages).
// ---------------------------------------------------------------------------
template<int CIN, int KTILE, int NTILE>
__global__ void __launch_bounds__(256)
conv_kernel(const float* __restrict__ A, const float* __restrict__ W,
            int COUT, int soff)
{
    constexpr int MTILE = 128, TM = 8, TX = 16;
    constexpr int TN = NTILE / TX;          // 4 or 8
    __shared__ float As[KTILE][MTILE + 4];  // [c][m]
    __shared__ float Ws[KTILE][NTILE + 4];  // [c][n]
    __shared__ double ssum[NTILE], ssq[NTILE];

    const int tid = threadIdx.x;
    const int tx = tid & 15, ty = tid >> 4;
    const int m0 = blockIdx.x * MTILE;
    const int n0 = blockIdx.y * NTILE;

    if (tid < NTILE) { ssum[tid] = 0.0; ssq[tid] = 0.0; }

    float acc[TM][TN];
    #pragma unroll
    for (int i = 0; i < TM; i++)
        #pragma unroll
        for (int j = 0; j < TN; j++) acc[i][j] = 0.0f;

    for (int kt = 0; kt < CIN; kt += KTILE) {
        __syncthreads();
        for (int e = tid; e < MTILE * KTILE; e += 256) {
            int m = e / KTILE, c = e - m * KTILE;
            As[c][m] = A[(size_t)(m0 + m) * CIN + kt + c];
        }
        for (int e = tid; e < NTILE * KTILE; e += 256) {
            int n = e / KTILE, c = e - n * KTILE;
            Ws[c][n] = W[(size_t)(n0 + n) * CIN + kt + c];
        }
        __syncthreads();

        #pragma unroll 4
        for (int c = 0; c < KTILE; c++) {
            float a[TM];
            #pragma unroll
            for (int i4 = 0; i4 < TM / 4; i4++) {
                float4 v = *(const float4*)&As[c][ty * TM + 4 * i4];
                a[4 * i4 + 0] = v.x; a[4 * i4 + 1] = v.y;
                a[4 * i4 + 2] = v.z; a[4 * i4 + 3] = v.w;
            }
            float bb[TN];
            #pragma unroll
            for (int j4 = 0; j4 < TN / 4; j4++) {
                float4 v = *(const float4*)&Ws[c][tx * TN + 4 * j4];
                bb[4 * j4 + 0] = v.x; bb[4 * j4 + 1] = v.y;
                bb[4 * j4 + 2] = v.z; bb[4 * j4 + 3] = v.w;
            }
            #pragma unroll
            for (int i = 0; i < TM; i++)
                #pragma unroll
                for (int j = 0; j < TN; j++)
                    acc[i][j] += a[i] * bb[j];
        }
    }

    // write Y (vectorized)
    #pragma unroll
    for (int i = 0; i < TM; i++) {
        size_t base = (size_t)(m0 + ty * TM + i) * COUT + n0 + tx * TN;
        #pragma unroll
        for (int j4 = 0; j4 < TN / 4; j4++) {
            float4 v = make_float4(acc[i][4 * j4 + 0], acc[i][4 * j4 + 1],
                                   acc[i][4 * j4 + 2], acc[i][4 * j4 + 3]);
            *(float4*)&g_y[base + 4 * j4] = v;
        }
    }

    // per-channel partial sums -> shared -> global
    #pragma unroll
    for (int j = 0; j < TN; j++) {
        float s = 0.0f, q = 0.0f;
        #pragma unroll
        for (int i = 0; i < TM; i++) { s += acc[i][j]; q += acc[i][j] * acc[i][j]; }
        atomicAdd(&ssum[tx * TN + j], (double)s);
        atomicAdd(&ssq [tx * TN + j], (double)q);
    }
    __syncthreads();
    if (tid < NTILE) {
        atomicAdd(&g_sum[soff + n0 + tid], ssum[tid]);
        atomicAdd(&g_sq [soff + n0 + tid], ssq [tid]);
    }
}

// ---------------------------------------------------------------------------
__global__ void finalize_kernel(int off, int C, double cnt,
                                const float* __restrict__ g,
                                const float* __restrict__ bch)
{
    int o = blockIdx.x * blockDim.x + threadIdx.x;
    if (o >= C) return;
    double mu  = g_sum[off + o] / cnt;
    double var = g_sq [off + o] / cnt - mu * mu;
    float sc = g[o] * (float)(1.0 / sqrt(var + 1e-5));
    g_scale[off + o] = sc;
    g_bias [off + o] = bch[o] - (float)mu * sc;
}

// ---------------------------------------------------------------------------
// BN + LeakyReLU + (optional h write) + max over k=20 into g_cat.
// Grid exactly ROWS_*COUT/256 threads.
// ---------------------------------------------------------------------------
template<bool WRITE_H>
__global__ void __launch_bounds__(256)
apply_kernel(int COUT, int soff, int chanoff)
{
    int t = blockIdx.x * blockDim.x + threadIdx.x;
    int o = t % COUT;
    int r = t / COUT;
    float sc = g_scale[soff + o], bi = g_bias[soff + o];
    size_t base = (size_t)r * KNN_ * COUT + o;
    float mx = -3.4e38f;
    #pragma unroll
    for (int k = 0; k < KNN_; k++) {
        float v = g_y[base + (size_t)k * COUT];
        v = v * sc + bi;
        v = (v >= 0.0f) ? v : 0.2f * v;
        if (WRITE_H) g_h[base + (size_t)k * COUT] = v;
        mx = fmaxf(mx, v);
    }
    g_cat[(size_t)r * 512 + chanoff + o] = mx;
}

// ---------------------------------------------------------------------------
// Stage 5 epilogue: BN + LeakyReLU + transpose [B,N,1024] -> [B,1024,N]
// ---------------------------------------------------------------------------
__global__ void __launch_bounds__(256)
apply5_kernel(float* __restrict__ out)
{
    __shared__ float tile[32][33];
    const int b  = blockIdx.z;
    const int o0 = blockIdx.x * 32;
    const int n0 = blockIdx.y * 32;
    const int txx = threadIdx.x, tyy = threadIdx.y;

    float sc = g_scale[512 + o0 + txx], bi = g_bias[512 + o0 + txx];
    #pragma unroll
    for (int i = 0; i < 4; i++) {
        int n = n0 + tyy + i * 8;
        float v = g_y[((size_t)(b * N_ + n)) * 1024 + o0 + txx];
        v = v * sc + bi;
        v = (v >= 0.0f) ? v : 0.2f * v;
        tile[tyy + i * 8][txx] = v;
    }
    __syncthreads();
    #pragma unroll
    for (int i = 0; i < 4; i++) {
        int o = o0 + tyy + i * 8;
        out[((size_t)(b * 1024 + o)) * N_ + n0 + txx] = tile[txx][tyy + i * 8];
    }
}

// ---------------------------------------------------------------------------
extern "C" void kernel_launch(void* const* d_in, const int* in_sizes, int n_in,
                              void* d_out, int out_size)
{
    const float* x  = (const float*)d_in[0];
    const float* W1 = (const float*)d_in[1];
    const float* g1 = (const float*)d_in[2];
    const float* b1 = (const float*)d_in[3];
    const float* W2 = (const float*)d_in[4];
    const float* g2 = (const float*)d_in[5];
    const float* b2 = (const float*)d_in[6];
    const float* W3 = (const float*)d_in[7];
    const float* g3 = (const float*)d_in[8];
    const float* b3 = (const float*)d_in[9];
    const float* W4 = (const float*)d_in[10];
    const float* g4 = (const float*)d_in[11];
    const float* b4 = (const float*)d_in[12];
    const float* W5 = (const float*)d_in[13];
    const float* g5 = (const float*)d_in[14];
    const float* b5 = (const float*)d_in[15];
    float* out = (float*)d_out;

    void *p_h0 = nullptr, *p_h = nullptr, *p_cat = nullptr;
    cudaGetSymbolAddress(&p_h0,  g_h0);
    cudaGetSymbolAddress(&p_h,   g_h);
    cudaGetSymbolAddress(&p_cat, g_cat);
    const float* f_h0  = (const float*)p_h0;
    const float* f_h   = (const float*)p_h;
    const float* f_cat = (const float*)p_cat;

    const double CNT1 = (double)M1_;    // 327680
    const double CNT5 = (double)ROWS_;  // 16384
    const int MB = M1_ / 128;           // 2560 m-blocks

    zero_stats_kernel<<<6, 256>>>();
    knn_feat_kernel<<<dim3(N_, B_), 256>>>(x);

    // stage 1: 6 -> 64
    conv_kernel<6, 6, 64><<<dim3(MB, 1), 256>>>(f_h0, W1, 64, 0);
    finalize_kernel<<<1, 64>>>(0, 64, CNT1, g1, b1);
    apply_kernel<true><<<(ROWS_ * 64) / 256, 256>>>(64, 0, 0);

    // stage 2: 64 -> 64
    conv_kernel<64, 32, 64><<<dim3(MB, 1), 256>>>(f_h, W2, 64, 64);
    finalize_kernel<<<1, 64>>>(64, 64, CNT1, g2, b2);
    apply_kernel<true><<<(ROWS_ * 64) / 256, 256>>>(64, 64, 64);

    // stage 3: 64 -> 128
    conv_kernel<64, 32, 128><<<dim3(MB, 1), 256>>>(f_h, W3, 128, 128);
    finalize_kernel<<<1, 128>>>(128, 128, CNT1, g3, b3);
    apply_kernel<true><<<(ROWS_ * 128) / 256, 256>>>(128, 128, 128);

    // stage 4: 128 -> 256 (max only, no h write)
    conv_kernel<128, 32, 128><<<dim3(MB, 2), 256>>>(f_h, W4, 256, 256);
    finalize_kernel<<<1, 256>>>(256, 256, CNT1, g4, b4);
    apply_kernel<false><<<(ROWS_ * 256) / 256, 256>>>(256, 256, 256);

    // stage 5: 512 -> 1024 on [16384, 512]
    conv_kernel<512, 32, 128><<<dim3(ROWS_ / 128, 8), 256>>>(f_cat, W5, 1024, 512);
    finalize_kernel<<<4, 256>>>(512, 1024, CNT5, g5, b5);
    apply5_kernel<<<dim3(32, 64, B_), dim3(32, 8)>>>(out);

    (void)in_sizes; (void)n_in; (void)out_size;
}

// round 4
// speedup vs baseline: 1.1632x; 1.1632x over previous
#include <cuda_runtime.h>
#include <cuda_bf16.h>
#include <math.h>
#include <stdint.h>

// ---------------------------------------------------------------------------
// DGCNN forward, B=8, C=3, N=2048, K=20 — mma.sync bf16-split GEMM version
// ---------------------------------------------------------------------------

#define B_      8
#define N_      2048
#define KNN_    20
#define ROWS_   (B_ * N_)                 // 16384
#define M1_     (ROWS_ * KNN_)            // 327680

// Static device scratch
__device__ float          g_h0[M1_ * 6];
__device__ float          g_y [M1_ * 256];
__device__ __nv_bfloat16  g_hhi[M1_ * 128];
__device__ __nv_bfloat16  g_hlo[M1_ * 128];
__device__ __nv_bfloat16  g_cathi[ROWS_ * 512];
__device__ __nv_bfloat16  g_catlo[ROWS_ * 512];
__device__ double g_sum[1536];
__device__ double g_sq [1536];
__device__ float  g_scale[1536];
__device__ float  g_bias [1536];

// ---------------------------------------------------------------------------
__device__ __forceinline__ uint32_t smem_to_u32(const void* p) {
    uint32_t a;
    asm("{ .reg .u64 t; cvta.to.shared.u64 t, %1; cvt.u32.u64 %0, t; }" : "=r"(a) : "l"(p));
    return a;
}
__device__ __forceinline__ void ldsm_x4(uint32_t addr, uint32_t r[4]) {
    asm volatile("ldmatrix.sync.aligned.m8n8.x4.shared.b16 {%0,%1,%2,%3}, [%4];"
                 : "=r"(r[0]), "=r"(r[1]), "=r"(r[2]), "=r"(r[3]) : "r"(addr));
}
__device__ __forceinline__ void mma_bf16(float c[4], const uint32_t a[4], const uint32_t b[2]) {
    asm volatile("mma.sync.aligned.m16n8k16.row.col.f32.bf16.bf16.f32 "
                 "{%0,%1,%2,%3}, {%4,%5,%6,%7}, {%8,%9}, {%0,%1,%2,%3};"
                 : "+f"(c[0]), "+f"(c[1]), "+f"(c[2]), "+f"(c[3])
                 : "r"(a[0]), "r"(a[1]), "r"(a[2]), "r"(a[3]), "r"(b[0]), "r"(b[1]));
}

// ---------------------------------------------------------------------------
__global__ void zero_stats_kernel() {
    int t = blockIdx.x * blockDim.x + threadIdx.x;
    if (t < 1536) { g_sum[t] = 0.0; g_sq[t] = 0.0; }
}

// ---------------------------------------------------------------------------
// kNN + edge features (proven in R1)
// ---------------------------------------------------------------------------
__global__ void __launch_bounds__(256) knn_feat_kernel(const float* __restrict__ x) {
    __shared__ float xs0[N_], xs1[N_], xs2[N_];
    __shared__ float dist[N_];
    __shared__ float wval[8];
    __shared__ int   widx[8];
    __shared__ int   sel[KNN_];

    const int b = blockIdx.y;
    const int i = blockIdx.x;
    const int tid = threadIdx.x;
    const float* xb = x + (size_t)b * 3 * N_;

    for (int j = tid; j < N_; j += 256) {
        xs0[j] = xb[j];
        xs1[j] = xb[N_ + j];
        xs2[j] = xb[2 * N_ + j];
    }
    __syncthreads();

    const float p0 = xs0[i], p1 = xs1[i], p2 = xs2[i];
    const float xxi = p0 * p0 + p1 * p1 + p2 * p2;

    for (int j = tid; j < N_; j += 256) {
        float q0 = xs0[j], q1 = xs1[j], q2 = xs2[j];
        float inner = p0 * q0 + p1 * q1 + p2 * q2;
        float xxj = q0 * q0 + q1 * q1 + q2 * q2;
        dist[j] = 2.0f * inner - xxi - xxj;
    }
    __syncthreads();

    const int lane = tid & 31, warp = tid >> 5;
    for (int t = 0; t < KNN_; t++) {
        float v = -3.0e38f; int bj = N_;
        for (int j = tid; j < N_; j += 256) {
            float d = dist[j];
            if (d > v || (d == v && j < bj)) { v = d; bj = j; }
        }
        #pragma unroll
        for (int s = 16; s > 0; s >>= 1) {
            float ov = __shfl_down_sync(0xffffffffu, v, s);
            int   oj = __shfl_down_sync(0xffffffffu, bj, s);
            if (ov > v || (ov == v && oj < bj)) { v = ov; bj = oj; }
        }
        if (lane == 0) { wval[warp] = v; widx[warp] = bj; }
        __syncthreads();
        if (tid == 0) {
            float bv = wval[0]; int bbj = widx[0];
            #pragma unroll
            for (int w = 1; w < 8; w++)
                if (wval[w] > bv || (wval[w] == bv && widx[w] < bbj)) { bv = wval[w]; bbj = widx[w]; }
            sel[t] = bbj;
            dist[bbj] = -3.3e38f;
        }
        __syncthreads();
    }

    for (int e = tid; e < KNN_ * 6; e += 256) {
        int kk = e / 6, c = e - kk * 6;
        int j = sel[kk];
        float val;
        if      (c == 0) val = xs0[j] - p0;
        else if (c == 1) val = xs1[j] - p1;
        else if (c == 2) val = xs2[j] - p2;
        else if (c == 3) val = p0;
        else if (c == 4) val = p1;
        else             val = p2;
        g_h0[(((size_t)b * N_ + i) * KNN_ + kk) * 6 + c] = val;
    }
}

// ---------------------------------------------------------------------------
// Stage-1 scalar SGEMM (CIN=6) + stats (proven in R1)
// ---------------------------------------------------------------------------
template<int CIN, int KTILE, int NTILE>
__global__ void __launch_bounds__(256)
conv_kernel(const float* __restrict__ A, const float* __restrict__ W,
            int COUT, int soff)
{
    constexpr int MTILE = 128, TM = 8, TX = 16;
    constexpr int TN = NTILE / TX;
    __shared__ float As[KTILE][MTILE + 4];
    __shared__ float Ws[KTILE][NTILE + 4];
    __shared__ double ssum[NTILE], ssq[NTILE];

    const int tid = threadIdx.x;
    const int tx = tid & 15, ty = tid >> 4;
    const int m0 = blockIdx.x * MTILE;
    const int n0 = blockIdx.y * NTILE;

    if (tid < NTILE) { ssum[tid] = 0.0; ssq[tid] = 0.0; }

    float acc[TM][TN];
    #pragma unroll
    for (int i = 0; i < TM; i++)
        #pragma unroll
        for (int j = 0; j < TN; j++) acc[i][j] = 0.0f;

    for (int kt = 0; kt < CIN; kt += KTILE) {
        __syncthreads();
        for (int e = tid; e < MTILE * KTILE; e += 256) {
            int m = e / KTILE, c = e - m * KTILE;
            As[c][m] = A[(size_t)(m0 + m) * CIN + kt + c];
        }
        for (int e = tid; e < NTILE * KTILE; e += 256) {
            int n = e / KTILE, c = e - n * KTILE;
            Ws[c][n] = W[(size_t)(n0 + n) * CIN + kt + c];
        }
        __syncthreads();

        #pragma unroll
        for (int c = 0; c < KTILE; c++) {
            float a[TM];
            #pragma unroll
            for (int i4 = 0; i4 < TM / 4; i4++) {
                float4 v = *(const float4*)&As[c][ty * TM + 4 * i4];
                a[4 * i4 + 0] = v.x; a[4 * i4 + 1] = v.y;
                a[4 * i4 + 2] = v.z; a[4 * i4 + 3] = v.w;
            }
            float bb[TN];
            #pragma unroll
            for (int j4 = 0; j4 < TN / 4; j4++) {
                float4 v = *(const float4*)&Ws[c][tx * TN + 4 * j4];
                bb[4 * j4 + 0] = v.x; bb[4 * j4 + 1] = v.y;
                bb[4 * j4 + 2] = v.z; bb[4 * j4 + 3] = v.w;
            }
            #pragma unroll
            for (int i = 0; i < TM; i++)
                #pragma unroll
                for (int j = 0; j < TN; j++)
                    acc[i][j] += a[i] * bb[j];
        }
    }

    #pragma unroll
    for (int i = 0; i < TM; i++) {
        size_t base = (size_t)(m0 + ty * TM + i) * COUT + n0 + tx * TN;
        #pragma unroll
        for (int j4 = 0; j4 < TN / 4; j4++) {
            float4 v = make_float4(acc[i][4 * j4 + 0], acc[i][4 * j4 + 1],
                                   acc[i][4 * j4 + 2], acc[i][4 * j4 + 3]);
            *(float4*)&g_y[base + 4 * j4] = v;
        }
    }

    #pragma unroll
    for (int j = 0; j < TN; j++) {
        float s = 0.0f, q = 0.0f;
        #pragma unroll
        for (int i = 0; i < TM; i++) { s += acc[i][j]; q += acc[i][j] * acc[i][j]; }
        atomicAdd(&ssum[tx * TN + j], (double)s);
        atomicAdd(&ssq [tx * TN + j], (double)q);
    }
    __syncthreads();
    if (tid < NTILE) {
        atomicAdd(&g_sum[soff + n0 + tid], ssum[tid]);
        atomicAdd(&g_sq [soff + n0 + tid], ssq [tid]);
    }
}

// ---------------------------------------------------------------------------
// mma.sync bf16-split GEMM: Y[m0+128, n0+NT] = A[., CIN] * W[n0+NT, CIN]^T
// ---------------------------------------------------------------------------
template<int CIN, int NT>
__global__ void __launch_bounds__(256)
conv_mma_kernel(const __nv_bfloat16* __restrict__ Ahi,
                const __nv_bfloat16* __restrict__ Alo,
                const float* __restrict__ Wg,
                int COUT, int soff)
{
    constexpr int NCHUNK = CIN / 64;
    constexpr int NFRAG  = NT / 16;
    constexpr int LDA    = 144;
    constexpr int OFF_AHI  = 0;
    constexpr int OFF_ALO  = 128 * LDA;
    constexpr int OFF_BHI  = 2 * 128 * LDA;
    constexpr int OFF_BLO  = OFF_BHI + NT * LDA;
    constexpr int OFF_STAT = OFF_BLO + NT * LDA;

    extern __shared__ __align__(16) char sm[];
    const uint32_t sb = smem_to_u32(sm);

    const int tid  = threadIdx.x;
    const int wid  = tid >> 5, lane = tid & 31;
    const int wm   = wid & 3, wn = wid >> 2;
    const int m0   = blockIdx.x * 128;
    const int n0   = blockIdx.y * NT;

    float* ssumf = (float*)(sm + OFF_STAT);
    float* ssqf  = ssumf + NT;
    for (int j = tid; j < 2 * NT; j += 256) ssumf[j] = 0.0f;

    const int g = lane >> 3, l = lane & 7;
    const int rA = ((g & 1) ? 8 : 0) + l;
    const int kA = (g & 2) ? 8 : 0;
    const int rB = ((g & 2) ? 8 : 0) + l;
    const int kB = (g & 1) ? 8 : 0;

    float acc[2][NFRAG][4];
    #pragma unroll
    for (int mf = 0; mf < 2; mf++)
        #pragma unroll
        for (int nf = 0; nf < NFRAG; nf++)
            #pragma unroll
            for (int i = 0; i < 4; i++) acc[mf][nf][i] = 0.0f;

    for (int chunk = 0; chunk < NCHUNK; chunk++) {
        const int kt = chunk * 64;
        __syncthreads();

        #pragma unroll
        for (int it = 0; it < 4; it++) {
            int e = tid + it * 256;
            int m = e >> 3, u = e & 7;
            size_t gofs = (size_t)(m0 + m) * CIN + kt + u * 8;
            uint32_t so = (uint32_t)(m * LDA + u * 16);
            *(uint4*)(sm + OFF_AHI + so) = *(const uint4*)(Ahi + gofs);
            *(uint4*)(sm + OFF_ALO + so) = *(const uint4*)(Alo + gofs);
        }
        for (int e = tid; e < NT * 8; e += 256) {
            int n = e >> 3, u = e & 7;
            const float* wp = Wg + (size_t)(n0 + n) * CIN + kt + u * 8;
            float f[8];
            *(float4*)(f)     = *(const float4*)(wp);
            *(float4*)(f + 4) = *(const float4*)(wp + 4);
            uint32_t hw[4], lw[4];
            #pragma unroll
            for (int i = 0; i < 4; i++) {
                float a = f[2 * i], b = f[2 * i + 1];
                __nv_bfloat16 ha = __float2bfloat16_rn(a);
                __nv_bfloat16 hb = __float2bfloat16_rn(b);
                __nv_bfloat16 la = __float2bfloat16_rn(a - __bfloat162float(ha));
                __nv_bfloat16 lb = __float2bfloat16_rn(b - __bfloat162float(hb));
                hw[i] = (uint32_t)__bfloat16_as_ushort(ha) | ((uint32_t)__bfloat16_as_ushort(hb) << 16);
                lw[i] = (uint32_t)__bfloat16_as_ushort(la) | ((uint32_t)__bfloat16_as_ushort(lb) << 16);
            }
            uint32_t so = (uint32_t)(n * LDA + u * 16);
            *(uint4*)(sm + OFF_BHI + so) = make_uint4(hw[0], hw[1], hw[2], hw[3]);
            *(uint4*)(sm + OFF_BLO + so) = make_uint4(lw[0], lw[1], lw[2], lw[3]);
        }
        __syncthreads();

        #pragma unroll
        for (int ks = 0; ks < 4; ks++) {
            const int k0 = ks * 16;
            uint32_t ahi[2][4], alo[2][4];
            #pragma unroll
            for (int mf = 0; mf < 2; mf++) {
                uint32_t ao = (uint32_t)((wm * 32 + mf * 16 + rA) * LDA + (k0 + kA) * 2);
                ldsm_x4(sb + OFF_AHI + ao, ahi[mf]);
                ldsm_x4(sb + OFF_ALO + ao, alo[mf]);
            }
            uint32_t bhi[NFRAG][2], blo[NFRAG][2];
            #pragma unroll
            for (int nf2 = 0; nf2 < NFRAG / 2; nf2++) {
                uint32_t bo = (uint32_t)((wn * (NT / 2) + nf2 * 16 + rB) * LDA + (k0 + kB) * 2);
                uint32_t t[4];
                ldsm_x4(sb + OFF_BHI + bo, t);
                bhi[2 * nf2][0] = t[0]; bhi[2 * nf2][1] = t[1];
                bhi[2 * nf2 + 1][0] = t[2]; bhi[2 * nf2 + 1][1] = t[3];
                ldsm_x4(sb + OFF_BLO + bo, t);
                blo[2 * nf2][0] = t[0]; blo[2 * nf2][1] = t[1];
                blo[2 * nf2 + 1][0] = t[2]; blo[2 * nf2 + 1][1] = t[3];
            }
            #pragma unroll
            for (int mf = 0; mf < 2; mf++)
                #pragma unroll
                for (int nf = 0; nf < NFRAG; nf++) {
                    mma_bf16(acc[mf][nf], ahi[mf], bhi[nf]);
                    mma_bf16(acc[mf][nf], ahi[mf], blo[nf]);
                    mma_bf16(acc[mf][nf], alo[mf], bhi[nf]);
                }
        }
    }

    const int qr = lane >> 2, qc = (lane & 3) * 2;
    #pragma unroll
    for (int nf = 0; nf < NFRAG; nf++) {
        const int coln = wn * (NT / 2) + nf * 8 + qc;
        float s0 = 0.0f, s1 = 0.0f, q0 = 0.0f, q1 = 0.0f;
        #pragma unroll
        for (int mf = 0; mf < 2; mf++) {
            float c0 = acc[mf][nf][0], c1 = acc[mf][nf][1];
            float c2 = acc[mf][nf][2], c3 = acc[mf][nf][3];
            int row = m0 + wm * 32 + mf * 16 + qr;
            *(float2*)&g_y[(size_t)row * COUT + n0 + coln]       = make_float2(c0, c1);
            *(float2*)&g_y[(size_t)(row + 8) * COUT + n0 + coln] = make_float2(c2, c3);
            s0 += c0 + c2;  s1 += c1 + c3;
            q0 += c0 * c0 + c2 * c2;
            q1 += c1 * c1 + c3 * c3;
        }
        atomicAdd(&ssumf[coln],     s0);
        atomicAdd(&ssumf[coln + 1], s1);
        atomicAdd(&ssqf [coln],     q0);
        atomicAdd(&ssqf [coln + 1], q1);
    }
    __syncthreads();
    for (int j = tid; j < NT; j += 256) {
        atomicAdd(&g_sum[soff + n0 + j], (double)ssumf[j]);
        atomicAdd(&g_sq [soff + n0 + j], (double)ssqf[j]);
    }
}

template<int NT>
constexpr int conv_smem_size() {
    return 2 * 128 * 144 + 2 * NT * 144 + 8 * NT;
}

// ---------------------------------------------------------------------------
__global__ void finalize_kernel(int off, int C, double cnt,
                                const float* __restrict__ g,
                                const float* __restrict__ bch)
{
    int o = blockIdx.x * blockDim.x + threadIdx.x;
    if (o >= C) return;
    double mu  = g_sum[off + o] / cnt;
    double var = g_sq [off + o] / cnt - mu * mu;
    float sc = g[o] * (float)(1.0 / sqrt(var + 1e-5));
    g_scale[off + o] = sc;
    g_bias [off + o] = bch[o] - (float)mu * sc;
}

// ---------------------------------------------------------------------------
// BN + LeakyReLU + bf16 hi/lo h write (optional) + k-max into bf16 cat planes.
// One thread per (point, channel-pair); loops the 20 neighbors internally.
// ---------------------------------------------------------------------------
template<bool WRITE_H>
__global__ void __launch_bounds__(256)
apply_kernel(int COUT, int soff, int chanoff)
{
    int t = blockIdx.x * blockDim.x + threadIdx.x;
    int halfC = COUT >> 1;
    int o = (t % halfC) * 2;
    int r = t / halfC;                    // point index in [0, ROWS_)
    float sc0 = g_scale[soff + o],     bi0 = g_bias[soff + o];
    float sc1 = g_scale[soff + o + 1], bi1 = g_bias[soff + o + 1];
    size_t base = (size_t)r * KNN_ * COUT + o;
    float mx0 = -3.4e38f, mx1 = -3.4e38f;
    #pragma unroll
    for (int k = 0; k < KNN_; k++) {
        size_t idx = base + (size_t)k * COUT;
        float2 y = *(const float2*)&g_y[idx];
        float v0 = y.x * sc0 + bi0; v0 = (v0 >= 0.0f) ? v0 : 0.2f * v0;
        float v1 = y.y * sc1 + bi1; v1 = (v1 >= 0.0f) ? v1 : 0.2f * v1;
        if (WRITE_H) {
            __nv_bfloat16 h0 = __float2bfloat16_rn(v0);
            __nv_bfloat16 h1 = __float2bfloat16_rn(v1);
            __nv_bfloat16 l0 = __float2bfloat16_rn(v0 - __bfloat162float(h0));
            __nv_bfloat16 l1 = __float2bfloat16_rn(v1 - __bfloat162float(h1));
            *(uint32_t*)&g_hhi[idx] =
                (uint32_t)__bfloat16_as_ushort(h0) | ((uint32_t)__bfloat16_as_ushort(h1) << 16);
            *(uint32_t*)&g_hlo[idx] =
                (uint32_t)__bfloat16_as_ushort(l0) | ((uint32_t)__bfloat16_as_ushort(l1) << 16);
        }
        mx0 = fmaxf(mx0, v0);
        mx1 = fmaxf(mx1, v1);
    }
    size_t cidx = (size_t)r * 512 + chanoff + o;
    __nv_bfloat16 c0 = __float2bfloat16_rn(mx0);
    __nv_bfloat16 c1 = __float2bfloat16_rn(mx1);
    __nv_bfloat16 d0 = __float2bfloat16_rn(mx0 - __bfloat162float(c0));
    __nv_bfloat16 d1 = __float2bfloat16_rn(mx1 - __bfloat162float(c1));
    *(uint32_t*)&g_cathi[cidx] =
        (uint32_t)__bfloat16_as_ushort(c0) | ((uint32_t)__bfloat16_as_ushort(c1) << 16);
    *(uint32_t*)&g_catlo[cidx] =
        (uint32_t)__bfloat16_as_ushort(d0) | ((uint32_t)__bfloat16_as_ushort(d1) << 16);
}

// ---------------------------------------------------------------------------
__global__ void __launch_bounds__(256)
apply5_kernel(float* __restrict__ out)
{
    __shared__ float tile[32][33];
    const int b  = blockIdx.z;
    const int o0 = blockIdx.x * 32;
    const int n0 = blockIdx.y * 32;
    const int txx = threadIdx.x, tyy = threadIdx.y;

    float sc = g_scale[512 + o0 + txx], bi = g_bias[512 + o0 + txx];
    #pragma unroll
    for (int i = 0; i < 4; i++) {
        int n = n0 + tyy + i * 8;
        float v = g_y[((size_t)(b * N_ + n)) * 1024 + o0 + txx];
        v = v * sc + bi;
        v = (v >= 0.0f) ? v : 0.2f * v;
        tile[tyy + i * 8][txx] = v;
    }
    __syncthreads();
    #pragma unroll
    for (int i = 0; i < 4; i++) {
        int o = o0 + tyy + i * 8;
        out[((size_t)(b * 1024 + o)) * N_ + n0 + txx] = tile[txx][tyy + i * 8];
    }
}

// ---------------------------------------------------------------------------
extern "C" void kernel_launch(void* const* d_in, const int* in_sizes, int n_in,
                              void* d_out, int out_size)
{
    const float* x  = (const float*)d_in[0];
    const float* W1 = (const float*)d_in[1];
    const float* g1 = (const float*)d_in[2];
    const float* b1 = (const float*)d_in[3];
    const float* W2 = (const float*)d_in[4];
    const float* g2 = (const float*)d_in[5];
    const float* b2 = (const float*)d_in[6];
    const float* W3 = (const float*)d_in[7];
    const float* g3 = (const float*)d_in[8];
    const float* b3 = (const float*)d_in[9];
    const float* W4 = (const float*)d_in[10];
    const float* g4 = (const float*)d_in[11];
    const float* b4 = (const float*)d_in[12];
    const float* W5 = (const float*)d_in[13];
    const float* g5 = (const float*)d_in[14];
    const float* b5 = (const float*)d_in[15];
    float* out = (float*)d_out;

    void *p_h0 = nullptr, *p_hhi = nullptr, *p_hlo = nullptr;
    void *p_chi = nullptr, *p_clo = nullptr;
    cudaGetSymbolAddress(&p_h0,  g_h0);
    cudaGetSymbolAddress(&p_hhi, g_hhi);
    cudaGetSymbolAddress(&p_hlo, g_hlo);
    cudaGetSymbolAddress(&p_chi, g_cathi);
    cudaGetSymbolAddress(&p_clo, g_catlo);
    const float* f_h0 = (const float*)p_h0;
    const __nv_bfloat16* f_hhi = (const __nv_bfloat16*)p_hhi;
    const __nv_bfloat16* f_hlo = (const __nv_bfloat16*)p_hlo;
    const __nv_bfloat16* f_chi = (const __nv_bfloat16*)p_chi;
    const __nv_bfloat16* f_clo = (const __nv_bfloat16*)p_clo;

    cudaFuncSetAttribute(conv_mma_kernel<64, 64>,   cudaFuncAttributeMaxDynamicSharedMemorySize,
                         conv_smem_size<64>());
    cudaFuncSetAttribute(conv_mma_kernel<64, 128>,  cudaFuncAttributeMaxDynamicSharedMemorySize,
                         conv_smem_size<128>());
    cudaFuncSetAttribute(conv_mma_kernel<128, 128>, cudaFuncAttributeMaxDynamicSharedMemorySize,
                         conv_smem_size<128>());
    cudaFuncSetAttribute(conv_mma_kernel<512, 128>, cudaFuncAttributeMaxDynamicSharedMemorySize,
                         conv_smem_size<128>());

    const double CNT1 = (double)M1_;
    const double CNT5 = (double)ROWS_;
    const int MB = M1_ / 128;   // 2560

    zero_stats_kernel<<<6, 256>>>();
    knn_feat_kernel<<<dim3(N_, B_), 256>>>(x);

    // stage 1: 6 -> 64 (scalar fp32)
    conv_kernel<6, 6, 64><<<dim3(MB, 1), 256>>>(f_h0, W1, 64, 0);
    finalize_kernel<<<1, 64>>>(0, 64, CNT1, g1, b1);
    apply_kernel<true><<<(ROWS_ * (64 / 2)) / 256, 256>>>(64, 0, 0);

    // stage 2: 64 -> 64 (mma.sync)
    conv_mma_kernel<64, 64><<<dim3(MB, 1), 256, conv_smem_size<64>()>>>(
        f_hhi, f_hlo, W2, 64, 64);
    finalize_kernel<<<1, 64>>>(64, 64, CNT1, g2, b2);
    apply_kernel<true><<<(ROWS_ * (64 / 2)) / 256, 256>>>(64, 64, 64);

    // stage 3: 64 -> 128
    conv_mma_kernel<64, 128><<<dim3(MB, 1), 256, conv_smem_size<128>()>>>(
        f_hhi, f_hlo, W3, 128, 128);
    finalize_kernel<<<1, 128>>>(128, 128, CNT1, g3, b3);
    apply_kernel<true><<<(ROWS_ * (128 / 2)) / 256, 256>>>(128, 128, 128);

    // stage 4: 128 -> 256 (max only)
    conv_mma_kernel<128, 128><<<dim3(MB, 2), 256, conv_smem_size<128>()>>>(
        f_hhi, f_hlo, W4, 256, 256);
    finalize_kernel<<<1, 256>>>(256, 256, CNT1, g4, b4);
    apply_kernel<false><<<(ROWS_ * (256 / 2)) / 256, 256>>>(256, 256, 256);

    // stage 5: 512 -> 1024 on [16384, 512]
    conv_mma_kernel<512, 128><<<dim3(ROWS_ / 128, 8), 256, conv_smem_size<128>()>>>(
        f_chi, f_clo, W5, 1024, 512);
    finalize_kernel<<<4, 256>>>(512, 1024, CNT5, g5, b5);
    apply5_kernel<<<dim3(32, 64, B_), dim3(32, 8)>>>(out);

    (void)in_sizes; (void)n_in; (void)out_size;
}